// round 1
// baseline (speedup 1.0000x reference)
#include <cuda_runtime.h>
#include <math.h>

// Problem constants
#define SQ 2048
#define NH 16
#define DM 1024
#define DH 64

// Scratch (allocation-free: __device__ globals). Layout [head][seq][dhead].
__device__ float g_q[NH * SQ * DH];
__device__ float g_k[NH * SQ * DH];
__device__ float g_v[NH * SQ * DH];
__device__ float g_z[NH * SQ * DH];

// XOR swizzle for transposed smem tiles: keeps float4 quads intact,
// spreads column accesses across banks.
__device__ __forceinline__ int swz(int r, int c) {
    return c ^ (((r >> 2) & 15) << 2);
}

// ---------------------------------------------------------------------------
// Kernel A: per-head projection (2048x1024 @ 1024x64) + bias + RoPE
// grid (32 s-tiles, 16 heads, 3 {q,k,v}), 256 threads
// ---------------------------------------------------------------------------
__global__ __launch_bounds__(256, 1) void proj_rope_kernel(
    const float* __restrict__ xq, const float* __restrict__ xk, const float* __restrict__ xv,
    const float* __restrict__ WQ, const float* __restrict__ bQ,
    const float* __restrict__ WK, const float* __restrict__ bK,
    const float* __restrict__ WV, const float* __restrict__ bV)
{
    __shared__ float At[32][64];   // k-major, swizzled: At[k][s]
    __shared__ float Bs[32][64];   // natural:  Bs[k][e]
    __shared__ float Cs[64][65];   // result staging for rotary

    const int sblk  = blockIdx.x;
    const int h     = blockIdx.y;
    const int which = blockIdx.z;

    const float* X; const float* W; const float* bias; float* out;
    if (which == 0)      { X = xq; W = WQ; bias = bQ; out = g_q; }
    else if (which == 1) { X = xk; W = WK; bias = bK; out = g_k; }
    else                 { X = xv; W = WV; bias = bV; out = g_v; }

    const int tid = threadIdx.x;
    const int tx = tid & 15, ty = tid >> 4;
    const int s0 = sblk * 64;

    float acc[4][4] = {};

    for (int k0 = 0; k0 < DM; k0 += 32) {
        __syncthreads();
        // Load X tile 64(s) x 32(k), store transposed+swizzled
        #pragma unroll
        for (int i = 0; i < 2; i++) {
            int idx = tid + i * 256;
            int r  = idx >> 3;          // s row 0..63
            int c4 = (idx & 7) * 4;     // k col
            const float4 v = *(const float4*)&X[((size_t)(s0 + r) * NH + h) * DM + k0 + c4];
            At[c4 + 0][swz(c4 + 0, r)] = v.x;
            At[c4 + 1][swz(c4 + 1, r)] = v.y;
            At[c4 + 2][swz(c4 + 2, r)] = v.z;
            At[c4 + 3][swz(c4 + 3, r)] = v.w;
        }
        // Load W tile 32(k) x 64(e)
        #pragma unroll
        for (int i = 0; i < 2; i++) {
            int idx = tid + i * 256;
            int r  = idx >> 4;          // k row 0..31
            int c4 = (idx & 15) * 4;    // e col
            *(float4*)&Bs[r][c4] =
                *(const float4*)&W[((size_t)h * DM + k0 + r) * DH + c4];
        }
        __syncthreads();

        #pragma unroll 8
        for (int kk = 0; kk < 32; kk++) {
            float4 a4 = *(const float4*)&At[kk][swz(kk, ty * 4)];
            float4 b4 = *(const float4*)&Bs[kk][tx * 4];
            float a[4] = {a4.x, a4.y, a4.z, a4.w};
            float b[4] = {b4.x, b4.y, b4.z, b4.w};
            #pragma unroll
            for (int ri = 0; ri < 4; ri++)
                #pragma unroll
                for (int ci = 0; ci < 4; ci++)
                    acc[ri][ci] = fmaf(a[ri], b[ci], acc[ri][ci]);
        }
    }
    __syncthreads();

    // Stage result + bias into Cs so rotary can read paired (e +- 32) elements
    #pragma unroll
    for (int ri = 0; ri < 4; ri++)
        #pragma unroll
        for (int ci = 0; ci < 4; ci++)
            Cs[ty * 4 + ri][tx * 4 + ci] = acc[ri][ci] + bias[h * DH + tx * 4 + ci];
    __syncthreads();

    // log2(10000)/32
    const float LOG2_BASE_OVER_HALF = 0.41524101186092029f;

    #pragma unroll
    for (int ri = 0; ri < 4; ri++) {
        int r = ty * 4 + ri;
        int pos = s0 + r;
        #pragma unroll
        for (int ci = 0; ci < 4; ci++) {
            int e = tx * 4 + ci;
            float val;
            if (which < 2) {
                int j = e & 31;
                float inv_freq = exp2f(-(float)j * LOG2_BASE_OVER_HALF);
                float ang = (float)pos * inv_freq;
                float sn, cs;
                sincosf(ang, &sn, &cs);
                float x    = Cs[r][e];
                float flip = (e < 32) ? -Cs[r][e + 32] : Cs[r][e - 32];
                val = x * cs + flip * sn;
            } else {
                val = Cs[r][e];
            }
            out[((size_t)h * SQ + pos) * DH + e] = val;
        }
    }
}

// ---------------------------------------------------------------------------
// Kernel B: causal flash attention. grid (16 paired q-tiles, 16 heads).
// Each block processes q-tile blockIdx.x and q-tile (31 - blockIdx.x):
// total key-tile iterations per block = (x+1) + (32-x) = 33 (perfectly balanced).
// ---------------------------------------------------------------------------
__global__ __launch_bounds__(256, 1) void attn_kernel()
{
    __shared__ float QT[64][64];   // d-major, swizzled: QT[d][q]
    __shared__ float KT[64][64];   // d-major, swizzled: KT[d][k]; reused as PT[k][q]
    __shared__ float Vs[64][64];   // natural: Vs[k][e]

    const int h   = blockIdx.y;
    const int tid = threadIdx.x;
    const int tx = tid & 15, ty = tid >> 4;

    for (int rep = 0; rep < 2; rep++) {
        const int qb = rep ? (31 - (int)blockIdx.x) : (int)blockIdx.x;
        const int q0 = qb * 64;

        __syncthreads();  // protect smem reuse from previous rep
        // Load Q tile transposed+swizzled
        #pragma unroll
        for (int i = 0; i < 4; i++) {
            int idx = tid + i * 256;
            int r  = idx >> 4;           // q row 0..63
            int c4 = (idx & 15) * 4;     // d col
            float4 v = *(const float4*)&g_q[((size_t)h * SQ + q0 + r) * DH + c4];
            QT[c4 + 0][swz(c4 + 0, r)] = v.x;
            QT[c4 + 1][swz(c4 + 1, r)] = v.y;
            QT[c4 + 2][swz(c4 + 2, r)] = v.z;
            QT[c4 + 3][swz(c4 + 3, r)] = v.w;
        }

        float m[4], l[4], o[4][4] = {};
        #pragma unroll
        for (int ri = 0; ri < 4; ri++) { m[ri] = -1e30f; l[ri] = 0.f; }

        for (int kb = 0; kb <= qb; kb++) {
            __syncthreads();  // previous PV done reading KT/Vs (and QT visible on 1st iter)
            // Load K transposed+swizzled, V natural
            #pragma unroll
            for (int i = 0; i < 4; i++) {
                int idx = tid + i * 256;
                int r  = idx >> 4;
                int c4 = (idx & 15) * 4;
                size_t base = ((size_t)h * SQ + kb * 64 + r) * DH + c4;
                float4 kv = *(const float4*)&g_k[base];
                KT[c4 + 0][swz(c4 + 0, r)] = kv.x;
                KT[c4 + 1][swz(c4 + 1, r)] = kv.y;
                KT[c4 + 2][swz(c4 + 2, r)] = kv.z;
                KT[c4 + 3][swz(c4 + 3, r)] = kv.w;
                *(float4*)&Vs[r][c4] = *(const float4*)&g_v[base];
            }
            __syncthreads();

            // S = Q K^T fragment (4 q-rows x 4 k-cols per thread)
            float sf[4][4] = {};
            #pragma unroll 8
            for (int d = 0; d < 64; d++) {
                float4 a4 = *(const float4*)&QT[d][swz(d, ty * 4)];
                float4 b4 = *(const float4*)&KT[d][swz(d, tx * 4)];
                float a[4] = {a4.x, a4.y, a4.z, a4.w};
                float b[4] = {b4.x, b4.y, b4.z, b4.w};
                #pragma unroll
                for (int ri = 0; ri < 4; ri++)
                    #pragma unroll
                    for (int ci = 0; ci < 4; ci++)
                        sf[ri][ci] = fmaf(a[ri], b[ci], sf[ri][ci]);
            }

            // scale + causal mask
            const bool diag = (kb == qb);
            #pragma unroll
            for (int ri = 0; ri < 4; ri++) {
                int qg = q0 + ty * 4 + ri;
                #pragma unroll
                for (int ci = 0; ci < 4; ci++) {
                    int kg = kb * 64 + tx * 4 + ci;
                    float s = sf[ri][ci] * 0.125f;
                    if (diag && kg > qg) s = -1e30f;
                    sf[ri][ci] = s;
                }
            }

            // Online softmax. Row r lives on the 16 lanes sharing ty (xor 1,2,4,8).
            #pragma unroll
            for (int ri = 0; ri < 4; ri++) {
                float rmax = fmaxf(fmaxf(sf[ri][0], sf[ri][1]),
                                   fmaxf(sf[ri][2], sf[ri][3]));
                #pragma unroll
                for (int off = 8; off > 0; off >>= 1)
                    rmax = fmaxf(rmax, __shfl_xor_sync(0xffffffffu, rmax, off));
                float mnew = fmaxf(m[ri], rmax);
                float corr = __expf(m[ri] - mnew);
                float rsum = 0.f;
                #pragma unroll
                for (int ci = 0; ci < 4; ci++) {
                    float p = __expf(sf[ri][ci] - mnew);
                    sf[ri][ci] = p;
                    rsum += p;
                }
                #pragma unroll
                for (int off = 8; off > 0; off >>= 1)
                    rsum += __shfl_xor_sync(0xffffffffu, rsum, off);
                l[ri] = l[ri] * corr + rsum;
                m[ri] = mnew;
                #pragma unroll
                for (int ci = 0; ci < 4; ci++) o[ri][ci] *= corr;
            }

            __syncthreads();  // all threads done reading KT
            // Write P transposed into KT buffer: PT[k][q]
            #pragma unroll
            for (int ri = 0; ri < 4; ri++)
                #pragma unroll
                for (int ci = 0; ci < 4; ci++) {
                    int kc = tx * 4 + ci, qr = ty * 4 + ri;
                    KT[kc][swz(kc, qr)] = sf[ri][ci];
                }
            __syncthreads();

            // O += P V
            #pragma unroll 8
            for (int kj = 0; kj < 64; kj++) {
                float4 p4 = *(const float4*)&KT[kj][swz(kj, ty * 4)];
                float4 v4 = *(const float4*)&Vs[kj][tx * 4];
                float p[4] = {p4.x, p4.y, p4.z, p4.w};
                float v[4] = {v4.x, v4.y, v4.z, v4.w};
                #pragma unroll
                for (int ri = 0; ri < 4; ri++)
                    #pragma unroll
                    for (int ci = 0; ci < 4; ci++)
                        o[ri][ci] = fmaf(p[ri], v[ci], o[ri][ci]);
            }
        }

        // Normalize and write Z
        #pragma unroll
        for (int ri = 0; ri < 4; ri++) {
            float inv = 1.f / l[ri];
            int qg = q0 + ty * 4 + ri;
            #pragma unroll
            for (int ci = 0; ci < 4; ci++)
                g_z[((size_t)h * SQ + qg) * DH + tx * 4 + ci] = o[ri][ci] * inv;
        }
    }
}

// ---------------------------------------------------------------------------
// Kernel C: per-head output projection (2048x64 @ 64x1024) + b_O/16
// grid (32 s-tiles, 16 d-tiles, 16 heads), 256 threads
// ---------------------------------------------------------------------------
__global__ __launch_bounds__(256, 1) void outproj_kernel(
    const float* __restrict__ WO, const float* __restrict__ bO,
    float* __restrict__ out)
{
    __shared__ float Zt[64][64];   // e-major, swizzled: Zt[e][s]
    __shared__ float Ws[64][64];   // natural:  Ws[e][d]

    const int sblk = blockIdx.x;
    const int dblk = blockIdx.y;
    const int h    = blockIdx.z;
    const int tid = threadIdx.x;
    const int tx = tid & 15, ty = tid >> 4;
    const int s0 = sblk * 64, d0 = dblk * 64;

    #pragma unroll
    for (int i = 0; i < 4; i++) {
        int idx = tid + i * 256;
        int r  = idx >> 4;          // row 0..63
        int c4 = (idx & 15) * 4;
        float4 z = *(const float4*)&g_z[((size_t)h * SQ + s0 + r) * DH + c4];
        Zt[c4 + 0][swz(c4 + 0, r)] = z.x;
        Zt[c4 + 1][swz(c4 + 1, r)] = z.y;
        Zt[c4 + 2][swz(c4 + 2, r)] = z.z;
        Zt[c4 + 3][swz(c4 + 3, r)] = z.w;
        *(float4*)&Ws[r][c4] =
            *(const float4*)&WO[((size_t)h * DH + r) * DM + d0 + c4];
    }
    __syncthreads();

    float acc[4][4] = {};
    #pragma unroll 8
    for (int e = 0; e < 64; e++) {
        float4 a4 = *(const float4*)&Zt[e][swz(e, ty * 4)];
        float4 b4 = *(const float4*)&Ws[e][tx * 4];
        float a[4] = {a4.x, a4.y, a4.z, a4.w};
        float b[4] = {b4.x, b4.y, b4.z, b4.w};
        #pragma unroll
        for (int ri = 0; ri < 4; ri++)
            #pragma unroll
            for (int ci = 0; ci < 4; ci++)
                acc[ri][ci] = fmaf(a[ri], b[ci], acc[ri][ci]);
    }

    #pragma unroll
    for (int ri = 0; ri < 4; ri++) {
        int sg = s0 + ty * 4 + ri;
        #pragma unroll
        for (int ci = 0; ci < 4; ci++) {
            int dg = d0 + tx * 4 + ci;
            out[((size_t)sg * NH + h) * DM + dg] = acc[ri][ci] + bO[dg] * (1.0f / 16.0f);
        }
    }
}

// ---------------------------------------------------------------------------
extern "C" void kernel_launch(void* const* d_in, const int* in_sizes, int n_in,
                              void* d_out, int out_size)
{
    (void)in_sizes; (void)n_in; (void)out_size;
    const float* xq = (const float*)d_in[0];
    const float* xk = (const float*)d_in[1];
    const float* xv = (const float*)d_in[2];
    const float* WQ = (const float*)d_in[3];
    const float* bQ = (const float*)d_in[4];
    const float* WK = (const float*)d_in[5];
    const float* bK = (const float*)d_in[6];
    const float* WV = (const float*)d_in[7];
    const float* bV = (const float*)d_in[8];
    const float* WO = (const float*)d_in[9];
    const float* bO = (const float*)d_in[10];
    float* out = (float*)d_out;

    proj_rope_kernel<<<dim3(32, 16, 3), 256>>>(xq, xk, xv, WQ, bQ, WK, bK, WV, bV);
    attn_kernel<<<dim3(16, 16), 256>>>();
    outproj_kernel<<<dim3(32, 16, 16), 256>>>(WO, bO, out);
}